// round 3
// baseline (speedup 1.0000x reference)
#include <cuda_runtime.h>
#include <cuda_bf16.h>
#include <math.h>

// Problem constants
#define B_   4
#define NO_  64
#define DO_  13
#define H_   256
#define NP_  32768

// Scratch (device globals; no allocation allowed)
__device__ float g_Anorm[B_*NO_*NO_];   // normalized adjacency
__device__ float g_mobj [B_*NO_*DO_];   // aggregated edge messages
__device__ float g_objM [B_*NO_*12];    // per-object affine map: c(3), M(9)

__device__ __forceinline__ float gelu_exact(float x) {
    return 0.5f * x * (1.0f + erff(x * 0.7071067811865476f));
}

// ---- packed f32x2 helpers (FFMA2: 2 fp32 FMAs per issue, bit-exact) ----
__device__ __forceinline__ void ffma2(unsigned long long& a,
                                      unsigned long long x,
                                      unsigned long long w) {
    asm("fma.rn.f32x2 %0, %1, %2, %0;" : "+l"(a) : "l"(x), "l"(w));
}
__device__ __forceinline__ unsigned long long pack2(float lo, float hi) {
    unsigned long long r;
    asm("mov.b64 %0, {%1, %2};" : "=l"(r) : "f"(lo), "f"(hi));
    return r;
}
__device__ __forceinline__ void unpack2(unsigned long long v, float& lo, float& hi) {
    asm("mov.b64 {%0, %1}, %2;" : "=f"(lo), "=f"(hi) : "l"(v));
}

// ---------------------------------------------------------------------------
// K0: adjacency + rigid-body precompute + dx_o cols [0:3] and [6:10]
// grid = B, block = 64
// ---------------------------------------------------------------------------
__global__ void k0_obj_prep(const float* __restrict__ xo,
                            float* __restrict__ Anorm,
                            float* __restrict__ objM,
                            float* __restrict__ dxo) {
    int b = blockIdx.x;
    int i = threadIdx.x;
    __shared__ float pos[NO_][3];

    const float* xrow = xo + (b*NO_ + i)*DO_;
    float x[13];
#pragma unroll
    for (int k = 0; k < 13; k++) x[k] = xrow[k];
    pos[i][0] = x[0]; pos[i][1] = x[1]; pos[i][2] = x[2];
    __syncthreads();

    const float s2 = 0.3f * 0.3f;
    float rs = 0.0f;
    for (int j = 0; j < NO_; j++) {
        float dx = x[0]-pos[j][0], dy = x[1]-pos[j][1], dz = x[2]-pos[j][2];
        float d2 = dx*dx + dy*dy + dz*dz;
        float v = (j == i) ? 1.0f : expf(-d2 / s2);
        rs += v;
    }
    for (int j = 0; j < NO_; j++) {
        float dx = x[0]-pos[j][0], dy = x[1]-pos[j][1], dz = x[2]-pos[j][2];
        float d2 = dx*dx + dy*dy + dz*dz;
        float v = (j == i) ? 1.0f : expf(-d2 / s2);
        Anorm[(b*NO_ + i)*NO_ + j] = v / rs;
    }

    float w = x[6], ux = x[7], uy = x[8], uz = x[9];
    float ox = x[10], oy = x[11], oz = x[12];
    float ss = w*w - (ux*ux + uy*uy + uz*uz);
    float R00 = ss + 2.0f*ux*ux,        R01 = 2.0f*(ux*uy - w*uz), R02 = 2.0f*(ux*uz + w*uy);
    float R10 = 2.0f*(ux*uy + w*uz),    R11 = ss + 2.0f*uy*uy,     R12 = 2.0f*(uy*uz - w*ux);
    float R20 = 2.0f*(ux*uz - w*uy),    R21 = 2.0f*(uy*uz + w*ux), R22 = ss + 2.0f*uz*uz;
    float M00 = -oz*R10 + oy*R20, M01 = -oz*R11 + oy*R21, M02 = -oz*R12 + oy*R22;
    float M10 =  oz*R00 - ox*R20, M11 =  oz*R01 - ox*R21, M12 =  oz*R02 - ox*R22;
    float M20 = -oy*R00 + ox*R10, M21 = -oy*R01 + ox*R11, M22 = -oy*R02 + ox*R12;
    float c0 = x[3] - (M00*x[0] + M01*x[1] + M02*x[2]);
    float c1 = x[4] - (M10*x[0] + M11*x[1] + M12*x[2]);
    float c2 = x[5] - (M20*x[0] + M21*x[1] + M22*x[2]);

    float* om = objM + (b*NO_ + i)*12;
    om[0]=c0; om[1]=c1; om[2]=c2;
    om[3]=M00; om[4]=M01; om[5]=M02;
    om[6]=M10; om[7]=M11; om[8]=M12;
    om[9]=M20; om[10]=M21; om[11]=M22;

    float* orow = dxo + (b*NO_ + i)*DO_;
    orow[0] = x[3]; orow[1] = x[4]; orow[2] = x[5];
    float qw = x[6], qx = x[7], qy = x[8], qz = x[9];
    orow[6] = 0.5f * (-(ox*qx + oy*qy + oz*qz));
    orow[7] = 0.5f * ( ox*qw + oy*qz - oz*qy);
    orow[8] = 0.5f * (-ox*qz + oy*qw + oz*qx);
    orow[9] = 0.5f * ( ox*qy - oy*qx + oz*qw);
}

// ---------------------------------------------------------------------------
// K2: edge MLP (31->256->256->13) fused with A-weighted reduction -> m_obj
// grid = B*NO, block = 256.  FFMA2 + register-pipelined weight stream.
// ---------------------------------------------------------------------------
#define EPAD 68   // k-major row stride in floats

__global__ void __launch_bounds__(256, 2)
k2_edge(const float* __restrict__ xo, const float* __restrict__ tptr,
        const float* __restrict__ Anorm,
        const float* __restrict__ W0, const float* __restrict__ b0,
        const float* __restrict__ W1, const float* __restrict__ b1,
        const float* __restrict__ W2, const float* __restrict__ b2,
        float* __restrict__ mobj) {
    extern __shared__ float sm[];
    float* xo_s = sm;              // 64*13 = 832
    float* einT = sm + 832;        // 31*68
    float* Arow = einT + 2108;     // 64
    float* red  = Arow + 64;       // 8*13
    float* h0T  = red + 104;       // 256*68

    int tid = threadIdx.x;
    int b = blockIdx.x >> 6, i = blockIdx.x & 63;

    const float* xb = xo + b*NO_*DO_;
    for (int idx = tid; idx < NO_*DO_; idx += 256) xo_s[idx] = xb[idx];
    for (int idx = tid; idx < NO_; idx += 256) Arow[idx] = Anorm[(b*NO_ + i)*NO_ + idx];
    __syncthreads();

    float t = *tptr;
    float xi0 = xo_s[i*13+0], xi1 = xo_s[i*13+1], xi2 = xo_s[i*13+2];
    for (int idx = tid; idx < 31*64; idx += 256) {
        int k = idx >> 6, j = idx & 63;
        float v;
        if (k < 13) v = xo_s[i*13 + k];
        else if (k < 26) v = xo_s[j*13 + (k-13)];
        else if (k < 29) v = xo_s[j*13 + (k-26)] - xo_s[i*13 + (k-26)];
        else if (k == 29) {
            float dx = xo_s[j*13+0]-xi0, dy = xo_s[j*13+1]-xi1, dz = xo_s[j*13+2]-xi2;
            v = sqrtf(dx*dx + dy*dy + dz*dz);
        } else v = t;
        einT[k*EPAD + j] = v;
    }
    __syncthreads();

    unsigned long long acc2[32];
    // ---- layer 0: 31 -> 256 (full unroll: ptxas front-batches the 31 LDGs) ----
    {
        float bb = b0[tid];
        unsigned long long bb2 = pack2(bb, bb);
#pragma unroll
        for (int j = 0; j < 32; j++) acc2[j] = bb2;
#pragma unroll
        for (int k = 0; k < 31; k++) {
            float w = W0[k*H_ + tid];
            unsigned long long w2 = pack2(w, w);
            const ulonglong2* er = reinterpret_cast<const ulonglong2*>(&einT[k*EPAD]);
#pragma unroll
            for (int j4 = 0; j4 < 16; j4++) {
                ulonglong2 e = er[j4];
                ffma2(acc2[j4*2+0], e.x, w2);
                ffma2(acc2[j4*2+1], e.y, w2);
            }
        }
#pragma unroll
        for (int j2 = 0; j2 < 32; j2++) {
            float lo, hi;
            unpack2(acc2[j2], lo, hi);
            h0T[tid*EPAD + j2*2 + 0] = gelu_exact(lo);
            h0T[tid*EPAD + j2*2 + 1] = gelu_exact(hi);
        }
    }
    __syncthreads();

    // ---- layer 1: 256 -> 256, depth-4 register prefetch on the W1 stream ----
    {
        float bb = b1[tid];
        unsigned long long bb2 = pack2(bb, bb);
#pragma unroll
        for (int j = 0; j < 32; j++) acc2[j] = bb2;

        float wbuf[4];
#pragma unroll
        for (int p = 0; p < 4; p++) wbuf[p] = W1[p*H_ + tid];

        for (int k0 = 0; k0 < 256; k0 += 4) {
            float wn[4];
            int kb = (k0 + 4 < 256) ? (k0 + 4) : 0;  // clamp; last-iter values unused
#pragma unroll
            for (int p = 0; p < 4; p++) wn[p] = W1[(kb + p)*H_ + tid];
#pragma unroll
            for (int p = 0; p < 4; p++) {
                unsigned long long w2 = pack2(wbuf[p], wbuf[p]);
                const ulonglong2* hr = reinterpret_cast<const ulonglong2*>(&h0T[(k0+p)*EPAD]);
#pragma unroll
                for (int j4 = 0; j4 < 16; j4++) {
                    ulonglong2 h = hr[j4];
                    ffma2(acc2[j4*2+0], h.x, w2);
                    ffma2(acc2[j4*2+1], h.y, w2);
                }
            }
#pragma unroll
            for (int p = 0; p < 4; p++) wbuf[p] = wn[p];
        }
    }

    // ---- gelu + A-weighted sum over edges, then project with W2 ----
    float u = 0.0f;
#pragma unroll
    for (int j2 = 0; j2 < 32; j2++) {
        float lo, hi;
        unpack2(acc2[j2], lo, hi);
        u += Arow[j2*2+0] * gelu_exact(lo);
        u += Arow[j2*2+1] * gelu_exact(hi);
    }

    float vd[13];
#pragma unroll
    for (int d = 0; d < 13; d++) vd[d] = u * W2[tid*13 + d];
#pragma unroll
    for (int off = 16; off > 0; off >>= 1) {
#pragma unroll
        for (int d = 0; d < 13; d++) vd[d] += __shfl_down_sync(0xffffffffu, vd[d], off);
    }
    int warp = tid >> 5, lane = tid & 31;
    if (lane == 0) {
#pragma unroll
        for (int d = 0; d < 13; d++) red[warp*13 + d] = vd[d];
    }
    __syncthreads();
    if (tid < 13) {
        float s = b2[tid];
#pragma unroll
        for (int wp = 0; wp < 8; wp++) s += red[wp*13 + tid];
        mobj[(b*NO_ + i)*13 + tid] = s;
    }
}

// ---------------------------------------------------------------------------
// K3: both node MLPs (27->256->256->256->3), 8 rows per block, FFMA2,
// depth-8 register prefetch on the weight streams.
// grid = 64, block = 256
// ---------------------------------------------------------------------------
__global__ void __launch_bounds__(256)
k3_node(const float* __restrict__ xo, const float* __restrict__ mobj,
        const float* __restrict__ tptr,
        const float* __restrict__ vw0, const float* __restrict__ vb0,
        const float* __restrict__ vw1, const float* __restrict__ vb1,
        const float* __restrict__ vw2, const float* __restrict__ vb2,
        const float* __restrict__ vw3, const float* __restrict__ vb3,
        const float* __restrict__ ow0, const float* __restrict__ ob0,
        const float* __restrict__ ow1, const float* __restrict__ ob1,
        const float* __restrict__ ow2, const float* __restrict__ ob2,
        const float* __restrict__ ow3, const float* __restrict__ ob3,
        float* __restrict__ dxo) {
    __shared__ __align__(16) float inT[27*8];
    __shared__ __align__(16) float hA[256*8];
    __shared__ __align__(16) float hB[256*8];

    int tid = threadIdx.x;
    int mlp = blockIdx.x >> 5;
    int rem = blockIdx.x & 31;
    int b = rem >> 3, chunk = rem & 7;
    int i0 = chunk * 8;

    const float *W0, *B0, *W1, *B1, *W2, *B2, *W3, *B3;
    int col0;
    if (mlp == 0) { W0=vw0; B0=vb0; W1=vw1; B1=vb1; W2=vw2; B2=vb2; W3=vw3; B3=vb3; col0 = 3; }
    else          { W0=ow0; B0=ob0; W1=ow1; B1=ob1; W2=ow2; B2=ob2; W3=ow3; B3=ob3; col0 = 10; }

    float t = *tptr;
    for (int idx = tid; idx < 27*8; idx += 256) {
        int k = idx >> 3, r = idx & 7;
        int row = b*NO_ + i0 + r;
        float v;
        if (k < 13) v = xo[row*13 + k];
        else if (k < 26) v = mobj[row*13 + (k-13)];
        else v = t;
        inT[k*8 + r] = v;
    }
    __syncthreads();

    unsigned long long acc2[4];
    float av[8];

    // layer 0: 27 -> 256, full unroll
    {
        float bb = B0[tid];
        unsigned long long bb2 = pack2(bb, bb);
        acc2[0]=bb2; acc2[1]=bb2; acc2[2]=bb2; acc2[3]=bb2;
#pragma unroll
        for (int k = 0; k < 27; k++) {
            float w = W0[k*H_ + tid];
            unsigned long long w2 = pack2(w, w);
            const ulonglong2* ir = reinterpret_cast<const ulonglong2*>(&inT[k*8]);
            ulonglong2 p = ir[0], q = ir[1];
            ffma2(acc2[0], p.x, w2); ffma2(acc2[1], p.y, w2);
            ffma2(acc2[2], q.x, w2); ffma2(acc2[3], q.y, w2);
        }
        unpack2(acc2[0], av[0], av[1]); unpack2(acc2[1], av[2], av[3]);
        unpack2(acc2[2], av[4], av[5]); unpack2(acc2[3], av[6], av[7]);
#pragma unroll
        for (int r = 0; r < 8; r++) hA[tid*8 + r] = gelu_exact(av[r]);
    }
    __syncthreads();

#define K3_LAYER256(W, BV, SRC, DST)                                           \
    {                                                                          \
        float bb = BV[tid];                                                    \
        unsigned long long bb2 = pack2(bb, bb);                                \
        acc2[0]=bb2; acc2[1]=bb2; acc2[2]=bb2; acc2[3]=bb2;                    \
        float wbuf[8];                                                         \
        _Pragma("unroll")                                                      \
        for (int p = 0; p < 8; p++) wbuf[p] = W[p*H_ + tid];                   \
        for (int k0 = 0; k0 < 256; k0 += 8) {                                  \
            float wn[8];                                                       \
            int kb = (k0 + 8 < 256) ? (k0 + 8) : 0;                            \
            _Pragma("unroll")                                                  \
            for (int p = 0; p < 8; p++) wn[p] = W[(kb + p)*H_ + tid];          \
            _Pragma("unroll")                                                  \
            for (int p = 0; p < 8; p++) {                                      \
                unsigned long long w2 = pack2(wbuf[p], wbuf[p]);               \
                const ulonglong2* ir = reinterpret_cast<const ulonglong2*>(&SRC[(k0+p)*8]); \
                ulonglong2 pp = ir[0], qq = ir[1];                             \
                ffma2(acc2[0], pp.x, w2); ffma2(acc2[1], pp.y, w2);            \
                ffma2(acc2[2], qq.x, w2); ffma2(acc2[3], qq.y, w2);            \
            }                                                                  \
            _Pragma("unroll")                                                  \
            for (int p = 0; p < 8; p++) wbuf[p] = wn[p];                       \
        }                                                                      \
        unpack2(acc2[0], av[0], av[1]); unpack2(acc2[1], av[2], av[3]);        \
        unpack2(acc2[2], av[4], av[5]); unpack2(acc2[3], av[6], av[7]);        \
        _Pragma("unroll")                                                      \
        for (int r = 0; r < 8; r++) DST[tid*8 + r] = gelu_exact(av[r]);        \
    }                                                                          \
    __syncthreads();

    K3_LAYER256(W1, B1, hA, hB)
    K3_LAYER256(W2, B2, hB, hA)

    // layer 3: 256 -> 3, warp w handles local row w
    {
        int wp = tid >> 5, lane = tid & 31;
        float p0 = 0.0f, p1 = 0.0f, p2 = 0.0f;
#pragma unroll
        for (int k = lane; k < 256; k += 32) {
            float h = hA[k*8 + wp];
            p0 += h * W3[k*3 + 0];
            p1 += h * W3[k*3 + 1];
            p2 += h * W3[k*3 + 2];
        }
#pragma unroll
        for (int off = 16; off > 0; off >>= 1) {
            p0 += __shfl_down_sync(0xffffffffu, p0, off);
            p1 += __shfl_down_sync(0xffffffffu, p1, off);
            p2 += __shfl_down_sync(0xffffffffu, p2, off);
        }
        if (lane == 0) {
            int row = b*NO_ + i0 + wp;
            dxo[row*13 + col0 + 0] = p0 + B3[0];
            dxo[row*13 + col0 + 1] = p1 + B3[1];
            dxo[row*13 + col0 + 2] = p2 + B3[2];
        }
    }
}

// ---------------------------------------------------------------------------
// K4: particle update as F[n,0:12] = S[n,:] @ [c|M], then affine finalize.
// grid = (NP/256, B), block = 256
// ---------------------------------------------------------------------------
#define PPB  256
#define SPAD 36

__global__ void __launch_bounds__(256)
k4_particles(const float* __restrict__ xp, const float* __restrict__ S,
             const float* __restrict__ objM, float* __restrict__ dxp) {
    extern __shared__ float sm[];
    float* Ms  = sm;            // 64*12 = 768 floats
    float* Ssm = sm + 768;      // 256*36; also output staging

    int tid = threadIdx.x;
    int b = blockIdx.y;
    int n0 = blockIdx.x * PPB;

    for (int idx = tid; idx < NO_*12; idx += 256) Ms[idx] = objM[b*NO_*12 + idx];

    int n = n0 + tid;
    const float* xr = xp + ((long)b*NP_ + n)*13;
    float px = xr[10], py = xr[11], pz = xr[12];
    float cvx = xr[3], cvy = xr[4], cvz = xr[5];

    unsigned long long acc2[6];
#pragma unroll
    for (int j = 0; j < 6; j++) acc2[j] = 0ull;

    const float* Sbase = S + ((long)b*NP_ + n0)*NO_;

    for (int c = 0; c < 2; c++) {
        __syncthreads();
        {
            const float4* src = reinterpret_cast<const float4*>(Sbase + c*32);
#pragma unroll
            for (int k = 0; k < 8; k++) {
                int idx = k*256 + tid;
                int p = idx >> 3, j = idx & 7;
                float4 v = src[p*16 + j];
                *reinterpret_cast<float4*>(&Ssm[p*SPAD + j*4]) = v;
            }
        }
        __syncthreads();

        const float4* srow = reinterpret_cast<const float4*>(&Ssm[tid*SPAD]);
#pragma unroll
        for (int m4 = 0; m4 < 8; m4++) {
            float4 s4 = srow[m4];
#pragma unroll
            for (int e = 0; e < 4; e++) {
                int m = c*32 + m4*4 + e;
                float s = (e==0) ? s4.x : (e==1) ? s4.y : (e==2) ? s4.z : s4.w;
                unsigned long long s2v = pack2(s, s);
                const ulonglong2* mr = reinterpret_cast<const ulonglong2*>(Ms + m*12);
                ulonglong2 m0 = mr[0], m1 = mr[1], m2 = mr[2];
                ffma2(acc2[0], m0.x, s2v); ffma2(acc2[1], m0.y, s2v);
                ffma2(acc2[2], m1.x, s2v); ffma2(acc2[3], m1.y, s2v);
                ffma2(acc2[4], m2.x, s2v); ffma2(acc2[5], m2.y, s2v);
            }
        }
    }

    float a0,a1,a2,a3,a4,a5,a6,a7,a8,a9,a10,a11;
    unpack2(acc2[0], a0, a1);  unpack2(acc2[1], a2, a3);
    unpack2(acc2[2], a4, a5);  unpack2(acc2[3], a6, a7);
    unpack2(acc2[4], a8, a9);  unpack2(acc2[5], a10, a11);
    float f0 = a0 + a3*px + a4*py + a5*pz;
    float f1 = a1 + a6*px + a7*py + a8*pz;
    float f2 = a2 + a9*px + a10*py + a11*pz;

    __syncthreads();
    float* orow = &Ssm[tid*13];
    orow[0] = f0; orow[1] = f1; orow[2] = f2;
    orow[3] = f0 - cvx; orow[4] = f1 - cvy; orow[5] = f2 - cvz;
#pragma unroll
    for (int d = 6; d < 13; d++) orow[d] = 0.0f;
    __syncthreads();

    float* og = dxp + ((long)b*NP_ + n0)*13;
    for (int idx = tid; idx < PPB*13; idx += 256) og[idx] = Ssm[idx];
}

// ---------------------------------------------------------------------------
extern "C" void kernel_launch(void* const* d_in, const int* in_sizes, int n_in,
                              void* d_out, int out_size) {
    const float* t   = (const float*)d_in[0];
    const float* x_p = (const float*)d_in[1];
    const float* x_o = (const float*)d_in[2];
    const float* S   = (const float*)d_in[3];
    const float* ew0 = (const float*)d_in[4];  const float* eb0 = (const float*)d_in[5];
    const float* ew1 = (const float*)d_in[6];  const float* eb1 = (const float*)d_in[7];
    const float* ew2 = (const float*)d_in[8];  const float* eb2 = (const float*)d_in[9];
    const float* vw0 = (const float*)d_in[10]; const float* vb0 = (const float*)d_in[11];
    const float* vw1 = (const float*)d_in[12]; const float* vb1 = (const float*)d_in[13];
    const float* vw2 = (const float*)d_in[14]; const float* vb2 = (const float*)d_in[15];
    const float* vw3 = (const float*)d_in[16]; const float* vb3 = (const float*)d_in[17];
    const float* ow0 = (const float*)d_in[18]; const float* ob0 = (const float*)d_in[19];
    const float* ow1 = (const float*)d_in[20]; const float* ob1 = (const float*)d_in[21];
    const float* ow2 = (const float*)d_in[22]; const float* ob2 = (const float*)d_in[23];
    const float* ow3 = (const float*)d_in[24]; const float* ob3 = (const float*)d_in[25];

    float* out = (float*)d_out;
    float* dxp = out;                       // B*NP*13
    float* dxo = out + (long)B_*NP_*13;     // B*NO*13

    float* Anorm; cudaGetSymbolAddress((void**)&Anorm, g_Anorm);
    float* mobj;  cudaGetSymbolAddress((void**)&mobj,  g_mobj);
    float* objM;  cudaGetSymbolAddress((void**)&objM,  g_objM);

    k0_obj_prep<<<B_, NO_>>>(x_o, Anorm, objM, dxo);

    size_t sm2 = (832 + 2108 + 64 + 104 + 256*EPAD) * sizeof(float);
    cudaFuncSetAttribute(k2_edge, cudaFuncAttributeMaxDynamicSharedMemorySize, (int)sm2);
    k2_edge<<<B_*NO_, 256, sm2>>>(x_o, t, Anorm, ew0, eb0, ew1, eb1, ew2, eb2, mobj);

    k3_node<<<64, 256>>>(x_o, mobj, t,
                         vw0, vb0, vw1, vb1, vw2, vb2, vw3, vb3,
                         ow0, ob0, ow1, ob1, ow2, ob2, ow3, ob3,
                         dxo);

    size_t sm4 = (768 + PPB*SPAD) * sizeof(float);
    cudaFuncSetAttribute(k4_particles, cudaFuncAttributeMaxDynamicSharedMemorySize, (int)sm4);
    k4_particles<<<dim3(NP_/PPB, B_), 256, sm4>>>(x_p, S, objM, dxp);
}

// round 4
// speedup vs baseline: 1.0288x; 1.0288x over previous
#include <cuda_runtime.h>
#include <cuda_bf16.h>
#include <math.h>

// Problem constants
#define B_   4
#define NO_  64
#define DO_  13
#define H_   256
#define NP_  32768

// Scratch (device globals; no allocation allowed)
__device__ float g_Anorm[B_*NO_*NO_];   // normalized adjacency
__device__ float g_mobj [B_*NO_*DO_];   // aggregated edge messages
__device__ float g_objM [B_*NO_*12];    // per-object affine map: c(3), M(9)

__device__ __forceinline__ float gelu_exact(float x) {
    return 0.5f * x * (1.0f + erff(x * 0.7071067811865476f));
}

// ---- packed f32x2 helpers (FFMA2: 2 fp32 FMAs per issue, bit-exact) ----
__device__ __forceinline__ void ffma2(unsigned long long& a,
                                      unsigned long long x,
                                      unsigned long long w) {
    asm("fma.rn.f32x2 %0, %1, %2, %0;" : "+l"(a) : "l"(x), "l"(w));
}
__device__ __forceinline__ unsigned long long pack2(float lo, float hi) {
    unsigned long long r;
    asm("mov.b64 %0, {%1, %2};" : "=l"(r) : "f"(lo), "f"(hi));
    return r;
}
__device__ __forceinline__ void unpack2(unsigned long long v, float& lo, float& hi) {
    asm("mov.b64 {%0, %1}, %2;" : "=f"(lo), "=f"(hi) : "l"(v));
}

// ---------------------------------------------------------------------------
// K0: adjacency + rigid-body precompute + dx_o cols [0:3] and [6:10]
// grid = B, block = 64
// ---------------------------------------------------------------------------
__global__ void k0_obj_prep(const float* __restrict__ xo,
                            float* __restrict__ Anorm,
                            float* __restrict__ objM,
                            float* __restrict__ dxo) {
    int b = blockIdx.x;
    int i = threadIdx.x;
    __shared__ float pos[NO_][3];

    const float* xrow = xo + (b*NO_ + i)*DO_;
    float x[13];
#pragma unroll
    for (int k = 0; k < 13; k++) x[k] = xrow[k];
    pos[i][0] = x[0]; pos[i][1] = x[1]; pos[i][2] = x[2];
    __syncthreads();

    const float s2 = 0.3f * 0.3f;
    float rs = 0.0f;
    for (int j = 0; j < NO_; j++) {
        float dx = x[0]-pos[j][0], dy = x[1]-pos[j][1], dz = x[2]-pos[j][2];
        float d2 = dx*dx + dy*dy + dz*dz;
        float v = (j == i) ? 1.0f : expf(-d2 / s2);
        rs += v;
    }
    for (int j = 0; j < NO_; j++) {
        float dx = x[0]-pos[j][0], dy = x[1]-pos[j][1], dz = x[2]-pos[j][2];
        float d2 = dx*dx + dy*dy + dz*dz;
        float v = (j == i) ? 1.0f : expf(-d2 / s2);
        Anorm[(b*NO_ + i)*NO_ + j] = v / rs;
    }

    float w = x[6], ux = x[7], uy = x[8], uz = x[9];
    float ox = x[10], oy = x[11], oz = x[12];
    float ss = w*w - (ux*ux + uy*uy + uz*uz);
    float R00 = ss + 2.0f*ux*ux,        R01 = 2.0f*(ux*uy - w*uz), R02 = 2.0f*(ux*uz + w*uy);
    float R10 = 2.0f*(ux*uy + w*uz),    R11 = ss + 2.0f*uy*uy,     R12 = 2.0f*(uy*uz - w*ux);
    float R20 = 2.0f*(ux*uz - w*uy),    R21 = 2.0f*(uy*uz + w*ux), R22 = ss + 2.0f*uz*uz;
    float M00 = -oz*R10 + oy*R20, M01 = -oz*R11 + oy*R21, M02 = -oz*R12 + oy*R22;
    float M10 =  oz*R00 - ox*R20, M11 =  oz*R01 - ox*R21, M12 =  oz*R02 - ox*R22;
    float M20 = -oy*R00 + ox*R10, M21 = -oy*R01 + ox*R11, M22 = -oy*R02 + ox*R12;
    float c0 = x[3] - (M00*x[0] + M01*x[1] + M02*x[2]);
    float c1 = x[4] - (M10*x[0] + M11*x[1] + M12*x[2]);
    float c2 = x[5] - (M20*x[0] + M21*x[1] + M22*x[2]);

    float* om = objM + (b*NO_ + i)*12;
    om[0]=c0; om[1]=c1; om[2]=c2;
    om[3]=M00; om[4]=M01; om[5]=M02;
    om[6]=M10; om[7]=M11; om[8]=M12;
    om[9]=M20; om[10]=M21; om[11]=M22;

    float* orow = dxo + (b*NO_ + i)*DO_;
    orow[0] = x[3]; orow[1] = x[4]; orow[2] = x[5];
    float qw = x[6], qx = x[7], qy = x[8], qz = x[9];
    orow[6] = 0.5f * (-(ox*qx + oy*qy + oz*qz));
    orow[7] = 0.5f * ( ox*qw + oy*qz - oz*qy);
    orow[8] = 0.5f * (-ox*qz + oy*qw + oz*qx);
    orow[9] = 0.5f * ( ox*qy - oy*qx + oz*qw);
}

// ---------------------------------------------------------------------------
// K2: edge MLP (31->256->256->13) fused with A-weighted reduction -> m_obj
// grid = B*NO, block = 512: thread = (channel c = tid&255, edge-half = tid>>8)
// Per-thread: 32 edges -> acc2[16] (32 regs).  FFMA2 inner loops.
// ---------------------------------------------------------------------------
#define EPAD 68   // k-major row stride in floats

__global__ void __launch_bounds__(512, 2)
k2_edge(const float* __restrict__ xo, const float* __restrict__ tptr,
        const float* __restrict__ Anorm,
        const float* __restrict__ W0, const float* __restrict__ b0,
        const float* __restrict__ W1, const float* __restrict__ b1,
        const float* __restrict__ W2, const float* __restrict__ b2,
        float* __restrict__ mobj) {
    extern __shared__ float sm[];
    float* xo_s = sm;              // 832
    float* einT = sm + 832;        // 31*68 = 2108
    float* Arow = einT + 2108;     // 64
    float* red  = Arow + 64;       // 16*13 = 208
    float* h0T  = red + 208;       // 256*68 (base float 3212 -> byte 12848, 16B-aligned)

    int tid = threadIdx.x;
    int c = tid & 255;
    int half = tid >> 8;
    int hoff = half * 32;
    int b = blockIdx.x >> 6, i = blockIdx.x & 63;

    const float* xb = xo + b*NO_*DO_;
    for (int idx = tid; idx < NO_*DO_; idx += 512) xo_s[idx] = xb[idx];
    for (int idx = tid; idx < NO_; idx += 512) Arow[idx] = Anorm[(b*NO_ + i)*NO_ + idx];
    __syncthreads();

    float t = *tptr;
    float xi0 = xo_s[i*13+0], xi1 = xo_s[i*13+1], xi2 = xo_s[i*13+2];
    for (int idx = tid; idx < 31*64; idx += 512) {
        int k = idx >> 6, j = idx & 63;
        float v;
        if (k < 13) v = xo_s[i*13 + k];
        else if (k < 26) v = xo_s[j*13 + (k-13)];
        else if (k < 29) v = xo_s[j*13 + (k-26)] - xo_s[i*13 + (k-26)];
        else if (k == 29) {
            float dx = xo_s[j*13+0]-xi0, dy = xo_s[j*13+1]-xi1, dz = xo_s[j*13+2]-xi2;
            v = sqrtf(dx*dx + dy*dy + dz*dz);
        } else v = t;
        einT[k*EPAD + j] = v;
    }
    __syncthreads();

    unsigned long long acc2[16];
    // ---- layer 0: 31 -> 256 over this thread's 32 edges ----
    {
        float bb = b0[c];
        unsigned long long bb2 = pack2(bb, bb);
#pragma unroll
        for (int j = 0; j < 16; j++) acc2[j] = bb2;
#pragma unroll
        for (int k = 0; k < 31; k++) {
            float w = W0[k*H_ + c];
            unsigned long long w2 = pack2(w, w);
            const ulonglong2* er = reinterpret_cast<const ulonglong2*>(&einT[k*EPAD + hoff]);
#pragma unroll
            for (int j4 = 0; j4 < 8; j4++) {
                ulonglong2 e = er[j4];
                ffma2(acc2[j4*2+0], e.x, w2);
                ffma2(acc2[j4*2+1], e.y, w2);
            }
        }
#pragma unroll
        for (int j2 = 0; j2 < 16; j2++) {
            float lo, hi;
            unpack2(acc2[j2], lo, hi);
            h0T[c*EPAD + hoff + j2*2 + 0] = gelu_exact(lo);
            h0T[c*EPAD + hoff + j2*2 + 1] = gelu_exact(hi);
        }
    }
    __syncthreads();

    // ---- layer 1: 256 -> 256, depth-4 register prefetch on the W1 stream ----
    {
        float bb = b1[c];
        unsigned long long bb2 = pack2(bb, bb);
#pragma unroll
        for (int j = 0; j < 16; j++) acc2[j] = bb2;

        float wbuf[4];
#pragma unroll
        for (int p = 0; p < 4; p++) wbuf[p] = W1[p*H_ + c];

        for (int k0 = 0; k0 < 256; k0 += 4) {
            float wn[4];
            int kb = (k0 + 4 < 256) ? (k0 + 4) : 0;  // clamp; last-iter values unused
#pragma unroll
            for (int p = 0; p < 4; p++) wn[p] = W1[(kb + p)*H_ + c];
#pragma unroll
            for (int p = 0; p < 4; p++) {
                unsigned long long w2 = pack2(wbuf[p], wbuf[p]);
                const ulonglong2* hr = reinterpret_cast<const ulonglong2*>(&h0T[(k0+p)*EPAD + hoff]);
#pragma unroll
                for (int j4 = 0; j4 < 8; j4++) {
                    ulonglong2 h = hr[j4];
                    ffma2(acc2[j4*2+0], h.x, w2);
                    ffma2(acc2[j4*2+1], h.y, w2);
                }
            }
#pragma unroll
            for (int p = 0; p < 4; p++) wbuf[p] = wn[p];
        }
    }

    // ---- gelu + A-weighted sum over this thread's 32 edges, project W2 ----
    float u = 0.0f;
#pragma unroll
    for (int j2 = 0; j2 < 16; j2++) {
        float lo, hi;
        unpack2(acc2[j2], lo, hi);
        u += Arow[hoff + j2*2+0] * gelu_exact(lo);
        u += Arow[hoff + j2*2+1] * gelu_exact(hi);
    }

    float vd[13];
#pragma unroll
    for (int d = 0; d < 13; d++) vd[d] = u * W2[c*13 + d];
#pragma unroll
    for (int off = 16; off > 0; off >>= 1) {
#pragma unroll
        for (int d = 0; d < 13; d++) vd[d] += __shfl_down_sync(0xffffffffu, vd[d], off);
    }
    int warp = tid >> 5, lane = tid & 31;
    if (lane == 0) {
#pragma unroll
        for (int d = 0; d < 13; d++) red[warp*13 + d] = vd[d];
    }
    __syncthreads();
    if (tid < 13) {
        float s = b2[tid];
#pragma unroll
        for (int wp = 0; wp < 16; wp++) s += red[wp*13 + tid];
        mobj[(b*NO_ + i)*13 + tid] = s;
    }
}

// ---------------------------------------------------------------------------
// K3: both node MLPs (27->256->256->256->3), 4 rows per block, FFMA2,
// depth-16 register prefetch.  grid = 128 (2 mlps x 4 b x 16 rowgroups)
// ---------------------------------------------------------------------------
__global__ void __launch_bounds__(256)
k3_node(const float* __restrict__ xo, const float* __restrict__ mobj,
        const float* __restrict__ tptr,
        const float* __restrict__ vw0, const float* __restrict__ vb0,
        const float* __restrict__ vw1, const float* __restrict__ vb1,
        const float* __restrict__ vw2, const float* __restrict__ vb2,
        const float* __restrict__ vw3, const float* __restrict__ vb3,
        const float* __restrict__ ow0, const float* __restrict__ ob0,
        const float* __restrict__ ow1, const float* __restrict__ ob1,
        const float* __restrict__ ow2, const float* __restrict__ ob2,
        const float* __restrict__ ow3, const float* __restrict__ ob3,
        float* __restrict__ dxo) {
    __shared__ __align__(16) float inT[27*4];
    __shared__ __align__(16) float hA[256*4];
    __shared__ __align__(16) float hB[256*4];

    int tid = threadIdx.x;
    int mlp = blockIdx.x >> 6;
    int rem = blockIdx.x & 63;
    int b = rem >> 4, grp = rem & 15;
    int i0 = grp * 4;

    const float *W0, *B0, *W1, *B1, *W2, *B2, *W3, *B3;
    int col0;
    if (mlp == 0) { W0=vw0; B0=vb0; W1=vw1; B1=vb1; W2=vw2; B2=vb2; W3=vw3; B3=vb3; col0 = 3; }
    else          { W0=ow0; B0=ob0; W1=ow1; B1=ob1; W2=ow2; B2=ob2; W3=ow3; B3=ob3; col0 = 10; }

    float t = *tptr;
    for (int idx = tid; idx < 27*4; idx += 256) {
        int k = idx >> 2, r = idx & 3;
        int row = b*NO_ + i0 + r;
        float v;
        if (k < 13) v = xo[row*13 + k];
        else if (k < 26) v = mobj[row*13 + (k-13)];
        else v = t;
        inT[k*4 + r] = v;
    }
    __syncthreads();

    unsigned long long acc2[2];
    float av[4];

    // layer 0: 27 -> 256, full unroll
    {
        float bb = B0[tid];
        unsigned long long bb2 = pack2(bb, bb);
        acc2[0]=bb2; acc2[1]=bb2;
#pragma unroll
        for (int k = 0; k < 27; k++) {
            float w = W0[k*H_ + tid];
            unsigned long long w2 = pack2(w, w);
            ulonglong2 pq = *reinterpret_cast<const ulonglong2*>(&inT[k*4]);
            ffma2(acc2[0], pq.x, w2);
            ffma2(acc2[1], pq.y, w2);
        }
        unpack2(acc2[0], av[0], av[1]); unpack2(acc2[1], av[2], av[3]);
#pragma unroll
        for (int r = 0; r < 4; r++) hA[tid*4 + r] = gelu_exact(av[r]);
    }
    __syncthreads();

#define K3_LAYER256(W, BV, SRC, DST)                                           \
    {                                                                          \
        float bb = BV[tid];                                                    \
        unsigned long long bb2 = pack2(bb, bb);                                \
        acc2[0]=bb2; acc2[1]=bb2;                                              \
        float wbuf[16];                                                        \
        _Pragma("unroll")                                                      \
        for (int p = 0; p < 16; p++) wbuf[p] = W[p*H_ + tid];                  \
        for (int k0 = 0; k0 < 256; k0 += 16) {                                 \
            float wn[16];                                                      \
            int kb = (k0 + 16 < 256) ? (k0 + 16) : 0;                          \
            _Pragma("unroll")                                                  \
            for (int p = 0; p < 16; p++) wn[p] = W[(kb + p)*H_ + tid];         \
            _Pragma("unroll")                                                  \
            for (int p = 0; p < 16; p++) {                                     \
                unsigned long long w2 = pack2(wbuf[p], wbuf[p]);               \
                ulonglong2 pq = *reinterpret_cast<const ulonglong2*>(&SRC[(k0+p)*4]); \
                ffma2(acc2[0], pq.x, w2);                                      \
                ffma2(acc2[1], pq.y, w2);                                      \
            }                                                                  \
            _Pragma("unroll")                                                  \
            for (int p = 0; p < 16; p++) wbuf[p] = wn[p];                      \
        }                                                                      \
        unpack2(acc2[0], av[0], av[1]); unpack2(acc2[1], av[2], av[3]);        \
        _Pragma("unroll")                                                      \
        for (int r = 0; r < 4; r++) DST[tid*4 + r] = gelu_exact(av[r]);        \
    }                                                                          \
    __syncthreads();

    K3_LAYER256(W1, B1, hA, hB)
    K3_LAYER256(W2, B2, hB, hA)

    // layer 3: 256 -> 3, warp wp (<4) handles local row wp
    {
        int wp = tid >> 5, lane = tid & 31;
        if (wp < 4) {
            float p0 = 0.0f, p1 = 0.0f, p2 = 0.0f;
#pragma unroll
            for (int k = lane; k < 256; k += 32) {
                float h = hA[k*4 + wp];
                p0 += h * W3[k*3 + 0];
                p1 += h * W3[k*3 + 1];
                p2 += h * W3[k*3 + 2];
            }
#pragma unroll
            for (int off = 16; off > 0; off >>= 1) {
                p0 += __shfl_down_sync(0xffffffffu, p0, off);
                p1 += __shfl_down_sync(0xffffffffu, p1, off);
                p2 += __shfl_down_sync(0xffffffffu, p2, off);
            }
            if (lane == 0) {
                int row = b*NO_ + i0 + wp;
                dxo[row*13 + col0 + 0] = p0 + B3[0];
                dxo[row*13 + col0 + 1] = p1 + B3[1];
                dxo[row*13 + col0 + 2] = p2 + B3[2];
            }
        }
    }
}

// ---------------------------------------------------------------------------
// K4: particle update as F[n,0:12] = S[n,:] @ [c|M], then affine finalize.
// x_p rows staged through smem (coalesced float4).  grid = (NP/256, B)
// ---------------------------------------------------------------------------
#define PPB  256
#define SPAD 36

__global__ void __launch_bounds__(256)
k4_particles(const float* __restrict__ xp, const float* __restrict__ S,
             const float* __restrict__ objM, float* __restrict__ dxp) {
    extern __shared__ float sm[];
    float* Ms  = sm;            // 768 floats
    float* Ssm = sm + 768;      // 256*36 = 9216; also output staging
    float* xps = sm + 768 + 9216; // 256*13 = 3328

    int tid = threadIdx.x;
    int b = blockIdx.y;
    int n0 = blockIdx.x * PPB;

    for (int idx = tid; idx < NO_*12; idx += 256) Ms[idx] = objM[b*NO_*12 + idx];

    // coalesced stage of 256 x_p rows (3328 floats = 832 float4)
    {
        const float4* xsrc = reinterpret_cast<const float4*>(xp + ((long)b*NP_ + n0)*13);
        float4* xdst = reinterpret_cast<float4*>(xps);
        for (int idx = tid; idx < 832; idx += 256) xdst[idx] = xsrc[idx];
    }
    __syncthreads();

    float px = xps[tid*13+10], py = xps[tid*13+11], pz = xps[tid*13+12];
    float cvx = xps[tid*13+3], cvy = xps[tid*13+4], cvz = xps[tid*13+5];

    unsigned long long acc2[6];
#pragma unroll
    for (int j = 0; j < 6; j++) acc2[j] = 0ull;

    const float* Sbase = S + ((long)b*NP_ + n0)*NO_;

    for (int c = 0; c < 2; c++) {
        __syncthreads();
        {
            const float4* src = reinterpret_cast<const float4*>(Sbase + c*32);
#pragma unroll
            for (int k = 0; k < 8; k++) {
                int idx = k*256 + tid;
                int p = idx >> 3, j = idx & 7;
                float4 v = src[p*16 + j];
                *reinterpret_cast<float4*>(&Ssm[p*SPAD + j*4]) = v;
            }
        }
        __syncthreads();

        const float4* srow = reinterpret_cast<const float4*>(&Ssm[tid*SPAD]);
#pragma unroll
        for (int m4 = 0; m4 < 8; m4++) {
            float4 s4 = srow[m4];
#pragma unroll
            for (int e = 0; e < 4; e++) {
                int m = c*32 + m4*4 + e;
                float s = (e==0) ? s4.x : (e==1) ? s4.y : (e==2) ? s4.z : s4.w;
                unsigned long long s2v = pack2(s, s);
                const ulonglong2* mr = reinterpret_cast<const ulonglong2*>(Ms + m*12);
                ulonglong2 m0 = mr[0], m1 = mr[1], m2 = mr[2];
                ffma2(acc2[0], m0.x, s2v); ffma2(acc2[1], m0.y, s2v);
                ffma2(acc2[2], m1.x, s2v); ffma2(acc2[3], m1.y, s2v);
                ffma2(acc2[4], m2.x, s2v); ffma2(acc2[5], m2.y, s2v);
            }
        }
    }

    float a0,a1,a2,a3,a4,a5,a6,a7,a8,a9,a10,a11;
    unpack2(acc2[0], a0, a1);  unpack2(acc2[1], a2, a3);
    unpack2(acc2[2], a4, a5);  unpack2(acc2[3], a6, a7);
    unpack2(acc2[4], a8, a9);  unpack2(acc2[5], a10, a11);
    float f0 = a0 + a3*px + a4*py + a5*pz;
    float f1 = a1 + a6*px + a7*py + a8*pz;
    float f2 = a2 + a9*px + a10*py + a11*pz;

    __syncthreads();
    float* orow = &Ssm[tid*13];
    orow[0] = f0; orow[1] = f1; orow[2] = f2;
    orow[3] = f0 - cvx; orow[4] = f1 - cvy; orow[5] = f2 - cvz;
#pragma unroll
    for (int d = 6; d < 13; d++) orow[d] = 0.0f;
    __syncthreads();

    float* og = dxp + ((long)b*NP_ + n0)*13;
    for (int idx = tid; idx < PPB*13; idx += 256) og[idx] = Ssm[idx];
}

// ---------------------------------------------------------------------------
extern "C" void kernel_launch(void* const* d_in, const int* in_sizes, int n_in,
                              void* d_out, int out_size) {
    const float* t   = (const float*)d_in[0];
    const float* x_p = (const float*)d_in[1];
    const float* x_o = (const float*)d_in[2];
    const float* S   = (const float*)d_in[3];
    const float* ew0 = (const float*)d_in[4];  const float* eb0 = (const float*)d_in[5];
    const float* ew1 = (const float*)d_in[6];  const float* eb1 = (const float*)d_in[7];
    const float* ew2 = (const float*)d_in[8];  const float* eb2 = (const float*)d_in[9];
    const float* vw0 = (const float*)d_in[10]; const float* vb0 = (const float*)d_in[11];
    const float* vw1 = (const float*)d_in[12]; const float* vb1 = (const float*)d_in[13];
    const float* vw2 = (const float*)d_in[14]; const float* vb2 = (const float*)d_in[15];
    const float* vw3 = (const float*)d_in[16]; const float* vb3 = (const float*)d_in[17];
    const float* ow0 = (const float*)d_in[18]; const float* ob0 = (const float*)d_in[19];
    const float* ow1 = (const float*)d_in[20]; const float* ob1 = (const float*)d_in[21];
    const float* ow2 = (const float*)d_in[22]; const float* ob2 = (const float*)d_in[23];
    const float* ow3 = (const float*)d_in[24]; const float* ob3 = (const float*)d_in[25];

    float* out = (float*)d_out;
    float* dxp = out;                       // B*NP*13
    float* dxo = out + (long)B_*NP_*13;     // B*NO*13

    float* Anorm; cudaGetSymbolAddress((void**)&Anorm, g_Anorm);
    float* mobj;  cudaGetSymbolAddress((void**)&mobj,  g_mobj);
    float* objM;  cudaGetSymbolAddress((void**)&objM,  g_objM);

    k0_obj_prep<<<B_, NO_>>>(x_o, Anorm, objM, dxo);

    size_t sm2 = (832 + 2108 + 64 + 208 + 256*EPAD) * sizeof(float);
    cudaFuncSetAttribute(k2_edge, cudaFuncAttributeMaxDynamicSharedMemorySize, (int)sm2);
    k2_edge<<<B_*NO_, 512, sm2>>>(x_o, t, Anorm, ew0, eb0, ew1, eb1, ew2, eb2, mobj);

    k3_node<<<128, 256>>>(x_o, mobj, t,
                          vw0, vb0, vw1, vb1, vw2, vb2, vw3, vb3,
                          ow0, ob0, ow1, ob1, ow2, ob2, ow3, ob3,
                          dxo);

    size_t sm4 = (768 + PPB*SPAD + PPB*13) * sizeof(float);
    cudaFuncSetAttribute(k4_particles, cudaFuncAttributeMaxDynamicSharedMemorySize, (int)sm4);
    k4_particles<<<dim3(NP_/PPB, B_), 256, sm4>>>(x_p, S, objM, dxp);
}

// round 5
// speedup vs baseline: 1.1357x; 1.1039x over previous
#include <cuda_runtime.h>
#include <cuda_bf16.h>
#include <math.h>

#define B_   4
#define NO_  64
#define DO_  13
#define H_   256
#define NP_  32768

// Scratch
__device__ float g_Anorm[B_*NO_*NO_];
__device__ float g_mobjp[2*B_*NO_*DO_];   // per-half partial edge messages
__device__ float g_objM [B_*NO_*12];

__device__ __forceinline__ float gelu_exact(float x) {
    return 0.5f * x * (1.0f + erff(x * 0.7071067811865476f));
}

__device__ __forceinline__ void ffma2(unsigned long long& a,
                                      unsigned long long x,
                                      unsigned long long w) {
    asm("fma.rn.f32x2 %0, %1, %2, %0;" : "+l"(a) : "l"(x), "l"(w));
}
__device__ __forceinline__ unsigned long long pack2(float lo, float hi) {
    unsigned long long r;
    asm("mov.b64 %0, {%1, %2};" : "=l"(r) : "f"(lo), "f"(hi));
    return r;
}
__device__ __forceinline__ void unpack2(unsigned long long v, float& lo, float& hi) {
    asm("mov.b64 {%0, %1}, %2;" : "=f"(lo), "=f"(hi) : "l"(v));
}

// ---------------------------------------------------------------------------
// K0: adjacency + rigid-body precompute + dx_o cols [0:3],[6:10]
// ---------------------------------------------------------------------------
__global__ void k0_obj_prep(const float* __restrict__ xo,
                            float* __restrict__ Anorm,
                            float* __restrict__ objM,
                            float* __restrict__ dxo) {
    int b = blockIdx.x;
    int i = threadIdx.x;
    __shared__ float pos[NO_][3];

    const float* xrow = xo + (b*NO_ + i)*DO_;
    float x[13];
#pragma unroll
    for (int k = 0; k < 13; k++) x[k] = xrow[k];
    pos[i][0] = x[0]; pos[i][1] = x[1]; pos[i][2] = x[2];
    __syncthreads();

    const float s2 = 0.3f * 0.3f;
    float rs = 0.0f;
    for (int j = 0; j < NO_; j++) {
        float dx = x[0]-pos[j][0], dy = x[1]-pos[j][1], dz = x[2]-pos[j][2];
        float d2 = dx*dx + dy*dy + dz*dz;
        float v = (j == i) ? 1.0f : expf(-d2 / s2);
        rs += v;
    }
    for (int j = 0; j < NO_; j++) {
        float dx = x[0]-pos[j][0], dy = x[1]-pos[j][1], dz = x[2]-pos[j][2];
        float d2 = dx*dx + dy*dy + dz*dz;
        float v = (j == i) ? 1.0f : expf(-d2 / s2);
        Anorm[(b*NO_ + i)*NO_ + j] = v / rs;
    }

    float w = x[6], ux = x[7], uy = x[8], uz = x[9];
    float ox = x[10], oy = x[11], oz = x[12];
    float ss = w*w - (ux*ux + uy*uy + uz*uz);
    float R00 = ss + 2.0f*ux*ux,        R01 = 2.0f*(ux*uy - w*uz), R02 = 2.0f*(ux*uz + w*uy);
    float R10 = 2.0f*(ux*uy + w*uz),    R11 = ss + 2.0f*uy*uy,     R12 = 2.0f*(uy*uz - w*ux);
    float R20 = 2.0f*(ux*uz - w*uy),    R21 = 2.0f*(uy*uz + w*ux), R22 = ss + 2.0f*uz*uz;
    float M00 = -oz*R10 + oy*R20, M01 = -oz*R11 + oy*R21, M02 = -oz*R12 + oy*R22;
    float M10 =  oz*R00 - ox*R20, M11 =  oz*R01 - ox*R21, M12 =  oz*R02 - ox*R22;
    float M20 = -oy*R00 + ox*R10, M21 = -oy*R01 + ox*R11, M22 = -oy*R02 + ox*R12;
    float c0 = x[3] - (M00*x[0] + M01*x[1] + M02*x[2]);
    float c1 = x[4] - (M10*x[0] + M11*x[1] + M12*x[2]);
    float c2 = x[5] - (M20*x[0] + M21*x[1] + M22*x[2]);

    float* om = objM + (b*NO_ + i)*12;
    om[0]=c0; om[1]=c1; om[2]=c2;
    om[3]=M00; om[4]=M01; om[5]=M02;
    om[6]=M10; om[7]=M11; om[8]=M12;
    om[9]=M20; om[10]=M21; om[11]=M22;

    float* orow = dxo + (b*NO_ + i)*DO_;
    orow[0] = x[3]; orow[1] = x[4]; orow[2] = x[5];
    float qw = x[6], qx = x[7], qy = x[8], qz = x[9];
    orow[6] = 0.5f * (-(ox*qx + oy*qy + oz*qz));
    orow[7] = 0.5f * ( ox*qw + oy*qz - oz*qy);
    orow[8] = 0.5f * (-ox*qz + oy*qw + oz*qx);
    orow[9] = 0.5f * ( ox*qy - oy*qx + oz*qw);
}

// ---------------------------------------------------------------------------
// K2: edge MLP register-tiled GEMM.
// grid = B*NO*2 (block = (b,i,half): 32 edges), block = 128 threads.
// Thread tile: 8 edges x 8 channels (channels ct+32q, interleaved).
// ---------------------------------------------------------------------------
#define HPAD 36

// smem layout (floats): xo_s[832] ein[31*36] Arow[32] h0T[256*36] red[1024] red2[52]
#define SM_XO   0
#define SM_EIN  832
#define SM_AR   1948
#define SM_H0   1980
#define SM_RED  11196
#define SM_RED2 12220
#define SM_TOT  12272   // 49088 bytes

__global__ void __launch_bounds__(128, 4)
k2_edge(const float* __restrict__ xo, const float* __restrict__ tptr,
        const float* __restrict__ Anorm,
        const float* __restrict__ W0, const float* __restrict__ b0,
        const float* __restrict__ W1, const float* __restrict__ b1,
        const float* __restrict__ W2, const float* __restrict__ b2,
        float* __restrict__ mobjp) {
    __shared__ __align__(16) float sm[SM_TOT];
    float* xo_s = sm + SM_XO;
    float* einT = sm + SM_EIN;
    float* Arow = sm + SM_AR;
    float* h0T  = sm + SM_H0;
    float* red  = sm + SM_RED;
    float* red2 = sm + SM_RED2;

    int tid = threadIdx.x;
    int half = blockIdx.x & 1;
    int bi = blockIdx.x >> 1;
    int b = bi >> 6, i = bi & 63;

    const float* xb = xo + b*NO_*DO_;
    for (int idx = tid; idx < NO_*DO_; idx += 128) xo_s[idx] = xb[idx];
    if (tid < 32) Arow[tid] = Anorm[(b*NO_ + i)*NO_ + half*32 + tid];
    __syncthreads();

    float t = *tptr;
    float xi0 = xo_s[i*13+0], xi1 = xo_s[i*13+1], xi2 = xo_s[i*13+2];
    for (int idx = tid; idx < 31*32; idx += 128) {
        int k = idx >> 5, e = idx & 31;
        int j = half*32 + e;
        float v;
        if (k < 13) v = xo_s[i*13 + k];
        else if (k < 26) v = xo_s[j*13 + (k-13)];
        else if (k < 29) v = xo_s[j*13 + (k-26)] - xo_s[i*13 + (k-26)];
        else if (k == 29) {
            float dx = xo_s[j*13+0]-xi0, dy = xo_s[j*13+1]-xi1, dz = xo_s[j*13+2]-xi2;
            v = sqrtf(dx*dx + dy*dy + dz*dz);
        } else v = t;
        einT[k*HPAD + e] = v;
    }
    __syncthreads();

    int ct = tid & 31;            // channel lane: owns channels ct + 32q, q=0..7
    int e0 = (tid >> 5) * 8;      // edge group: 8 edges
    int et = tid >> 5;            // warp id == edge group

    unsigned long long acc2[32];  // acc2[e*4+p] packs channels (ct+64p, ct+64p+32)

    // ---- layer 0: 31 -> 256 ----
    {
        unsigned long long bb2[4];
#pragma unroll
        for (int p = 0; p < 4; p++) bb2[p] = pack2(b0[ct + 64*p], b0[ct + 64*p + 32]);
#pragma unroll
        for (int e = 0; e < 8; e++)
#pragma unroll
            for (int p = 0; p < 4; p++) acc2[e*4+p] = bb2[p];

        for (int k = 0; k < 31; k++) {
            const float* wr = W0 + k*H_;
            unsigned long long w2[4];
#pragma unroll
            for (int p = 0; p < 4; p++) w2[p] = pack2(wr[ct + 64*p], wr[ct + 64*p + 32]);
            float4 a0 = *reinterpret_cast<const float4*>(&einT[k*HPAD + e0]);
            float4 a1 = *reinterpret_cast<const float4*>(&einT[k*HPAD + e0 + 4]);
            float av[8] = {a0.x,a0.y,a0.z,a0.w,a1.x,a1.y,a1.z,a1.w};
#pragma unroll
            for (int e = 0; e < 8; e++) {
                unsigned long long s2 = pack2(av[e], av[e]);
#pragma unroll
                for (int p = 0; p < 4; p++) ffma2(acc2[e*4+p], w2[p], s2);
            }
        }
#pragma unroll
        for (int e = 0; e < 8; e++)
#pragma unroll
            for (int p = 0; p < 4; p++) {
                float lo, hi; unpack2(acc2[e*4+p], lo, hi);
                h0T[(ct + 64*p)*HPAD + e0 + e]      = gelu_exact(lo);
                h0T[(ct + 64*p + 32)*HPAD + e0 + e] = gelu_exact(hi);
            }
    }
    __syncthreads();

    // ---- layer 1: 256 -> 256 ----
    {
        unsigned long long bb2[4];
#pragma unroll
        for (int p = 0; p < 4; p++) bb2[p] = pack2(b1[ct + 64*p], b1[ct + 64*p + 32]);
#pragma unroll
        for (int e = 0; e < 8; e++)
#pragma unroll
            for (int p = 0; p < 4; p++) acc2[e*4+p] = bb2[p];

        for (int k = 0; k < 256; k++) {
            const float* wr = W1 + k*H_;
            unsigned long long w2[4];
#pragma unroll
            for (int p = 0; p < 4; p++) w2[p] = pack2(wr[ct + 64*p], wr[ct + 64*p + 32]);
            float4 a0 = *reinterpret_cast<const float4*>(&h0T[k*HPAD + e0]);
            float4 a1 = *reinterpret_cast<const float4*>(&h0T[k*HPAD + e0 + 4]);
            float av[8] = {a0.x,a0.y,a0.z,a0.w,a1.x,a1.y,a1.z,a1.w};
#pragma unroll
            for (int e = 0; e < 8; e++) {
                unsigned long long s2 = pack2(av[e], av[e]);
#pragma unroll
                for (int p = 0; p < 4; p++) ffma2(acc2[e*4+p], w2[p], s2);
            }
        }
    }

    // ---- gelu + A-weighted sum over this thread's 8 edges ----
    {
        float u[8];
#pragma unroll
        for (int q = 0; q < 8; q++) u[q] = 0.0f;
#pragma unroll
        for (int e = 0; e < 8; e++) {
            float ae = Arow[e0 + e];
#pragma unroll
            for (int p = 0; p < 4; p++) {
                float lo, hi; unpack2(acc2[e*4+p], lo, hi);
                u[2*p]   += ae * gelu_exact(lo);
                u[2*p+1] += ae * gelu_exact(hi);
            }
        }
#pragma unroll
        for (int p = 0; p < 4; p++) {
            red[et*256 + ct + 64*p]      = u[2*p];
            red[et*256 + ct + 64*p + 32] = u[2*p+1];
        }
    }
    __syncthreads();

    // ---- combine 4 edge groups, project with W2 (13 outputs) ----
    {
        int c1 = tid, c2 = tid + 128;
        float f1 = red[c1] + red[256+c1] + red[512+c1] + red[768+c1];
        float f2 = red[c2] + red[256+c2] + red[512+c2] + red[768+c2];
        float vd[13];
#pragma unroll
        for (int d = 0; d < 13; d++)
            vd[d] = f1 * W2[c1*13 + d] + f2 * W2[c2*13 + d];
#pragma unroll
        for (int off = 16; off > 0; off >>= 1)
#pragma unroll
            for (int d = 0; d < 13; d++) vd[d] += __shfl_down_sync(0xffffffffu, vd[d], off);
        int warp = tid >> 5, lane = tid & 31;
        if (lane == 0)
#pragma unroll
            for (int d = 0; d < 13; d++) red2[warp*13 + d] = vd[d];
    }
    __syncthreads();
    if (tid < 13) {
        float s = (half == 0) ? b2[tid] : 0.0f;
#pragma unroll
        for (int wp = 0; wp < 4; wp++) s += red2[wp*13 + tid];
        mobjp[half*(B_*NO_*DO_) + (b*NO_ + i)*13 + tid] = s;
    }
}

// ---------------------------------------------------------------------------
// K3: both node MLPs (27->256->256->256->3), 4 rows/block, grid = 128
// ---------------------------------------------------------------------------
__global__ void __launch_bounds__(256)
k3_node(const float* __restrict__ xo, const float* __restrict__ mobjp,
        const float* __restrict__ tptr,
        const float* __restrict__ vw0, const float* __restrict__ vb0,
        const float* __restrict__ vw1, const float* __restrict__ vb1,
        const float* __restrict__ vw2, const float* __restrict__ vb2,
        const float* __restrict__ vw3, const float* __restrict__ vb3,
        const float* __restrict__ ow0, const float* __restrict__ ob0,
        const float* __restrict__ ow1, const float* __restrict__ ob1,
        const float* __restrict__ ow2, const float* __restrict__ ob2,
        const float* __restrict__ ow3, const float* __restrict__ ob3,
        float* __restrict__ dxo) {
    __shared__ __align__(16) float inT[27*4];
    __shared__ __align__(16) float hA[256*4];
    __shared__ __align__(16) float hB[256*4];

    int tid = threadIdx.x;
    int mlp = blockIdx.x >> 6;
    int rem = blockIdx.x & 63;
    int b = rem >> 4, grp = rem & 15;
    int i0 = grp * 4;

    const float *W0, *B0, *W1, *B1, *W2, *B2, *W3, *B3;
    int col0;
    if (mlp == 0) { W0=vw0; B0=vb0; W1=vw1; B1=vb1; W2=vw2; B2=vb2; W3=vw3; B3=vb3; col0 = 3; }
    else          { W0=ow0; B0=ob0; W1=ow1; B1=ob1; W2=ow2; B2=ob2; W3=ow3; B3=ob3; col0 = 10; }

    float t = *tptr;
    for (int idx = tid; idx < 27*4; idx += 256) {
        int k = idx >> 2, r = idx & 3;
        int row = b*NO_ + i0 + r;
        float v;
        if (k < 13) v = xo[row*13 + k];
        else if (k < 26) v = mobjp[row*13 + (k-13)] + mobjp[B_*NO_*DO_ + row*13 + (k-13)];
        else v = t;
        inT[k*4 + r] = v;
    }
    __syncthreads();

    unsigned long long acc2[2];
    float av[4];

    {
        float bb = B0[tid];
        unsigned long long bb2 = pack2(bb, bb);
        acc2[0]=bb2; acc2[1]=bb2;
#pragma unroll
        for (int k = 0; k < 27; k++) {
            float w = W0[k*H_ + tid];
            unsigned long long w2 = pack2(w, w);
            ulonglong2 pq = *reinterpret_cast<const ulonglong2*>(&inT[k*4]);
            ffma2(acc2[0], pq.x, w2);
            ffma2(acc2[1], pq.y, w2);
        }
        unpack2(acc2[0], av[0], av[1]); unpack2(acc2[1], av[2], av[3]);
#pragma unroll
        for (int r = 0; r < 4; r++) hA[tid*4 + r] = gelu_exact(av[r]);
    }
    __syncthreads();

#define K3_LAYER256(W, BV, SRC, DST)                                           \
    {                                                                          \
        float bb = BV[tid];                                                    \
        unsigned long long bb2 = pack2(bb, bb);                                \
        acc2[0]=bb2; acc2[1]=bb2;                                              \
        for (int k0 = 0; k0 < 256; k0 += 8) {                                  \
            _Pragma("unroll")                                                  \
            for (int p = 0; p < 8; p++) {                                      \
                float w = W[(k0+p)*H_ + tid];                                  \
                unsigned long long w2 = pack2(w, w);                           \
                ulonglong2 pq = *reinterpret_cast<const ulonglong2*>(&SRC[(k0+p)*4]); \
                ffma2(acc2[0], pq.x, w2);                                      \
                ffma2(acc2[1], pq.y, w2);                                      \
            }                                                                  \
        }                                                                      \
        unpack2(acc2[0], av[0], av[1]); unpack2(acc2[1], av[2], av[3]);        \
        _Pragma("unroll")                                                      \
        for (int r = 0; r < 4; r++) DST[tid*4 + r] = gelu_exact(av[r]);        \
    }                                                                          \
    __syncthreads();

    K3_LAYER256(W1, B1, hA, hB)
    K3_LAYER256(W2, B2, hB, hA)

    {
        int wp = tid >> 5, lane = tid & 31;
        if (wp < 4) {
            float p0 = 0.0f, p1 = 0.0f, p2 = 0.0f;
#pragma unroll
            for (int k = lane; k < 256; k += 32) {
                float h = hA[k*4 + wp];
                p0 += h * W3[k*3 + 0];
                p1 += h * W3[k*3 + 1];
                p2 += h * W3[k*3 + 2];
            }
#pragma unroll
            for (int off = 16; off > 0; off >>= 1) {
                p0 += __shfl_down_sync(0xffffffffu, p0, off);
                p1 += __shfl_down_sync(0xffffffffu, p1, off);
                p2 += __shfl_down_sync(0xffffffffu, p2, off);
            }
            if (lane == 0) {
                int row = b*NO_ + i0 + wp;
                dxo[row*13 + col0 + 0] = p0 + B3[0];
                dxo[row*13 + col0 + 1] = p1 + B3[1];
                dxo[row*13 + col0 + 2] = p2 + B3[2];
            }
        }
    }
}

// ---------------------------------------------------------------------------
// K4: particle update (reverted to the measured-fastest R2 form)
// ---------------------------------------------------------------------------
#define PPB  256
#define SPAD 36

__global__ void __launch_bounds__(256)
k4_particles(const float* __restrict__ xp, const float* __restrict__ S,
             const float* __restrict__ objM, float* __restrict__ dxp) {
    extern __shared__ float sm[];
    float* Ms  = sm;
    float* Ssm = sm + 768;

    int tid = threadIdx.x;
    int b = blockIdx.y;
    int n0 = blockIdx.x * PPB;

    for (int idx = tid; idx < NO_*12; idx += 256) Ms[idx] = objM[b*NO_*12 + idx];

    int n = n0 + tid;
    const float* xr = xp + ((long)b*NP_ + n)*13;
    float px = xr[10], py = xr[11], pz = xr[12];
    float cvx = xr[3], cvy = xr[4], cvz = xr[5];

    unsigned long long acc2[6];
#pragma unroll
    for (int j = 0; j < 6; j++) acc2[j] = 0ull;

    const float* Sbase = S + ((long)b*NP_ + n0)*NO_;

    for (int c = 0; c < 2; c++) {
        __syncthreads();
        {
            const float4* src = reinterpret_cast<const float4*>(Sbase + c*32);
#pragma unroll
            for (int k = 0; k < 8; k++) {
                int idx = k*256 + tid;
                int p = idx >> 3, j = idx & 7;
                float4 v = src[p*16 + j];
                *reinterpret_cast<float4*>(&Ssm[p*SPAD + j*4]) = v;
            }
        }
        __syncthreads();

        const float4* srow = reinterpret_cast<const float4*>(&Ssm[tid*SPAD]);
#pragma unroll
        for (int m4 = 0; m4 < 8; m4++) {
            float4 s4 = srow[m4];
#pragma unroll
            for (int e = 0; e < 4; e++) {
                int m = c*32 + m4*4 + e;
                float s = (e==0) ? s4.x : (e==1) ? s4.y : (e==2) ? s4.z : s4.w;
                unsigned long long s2v = pack2(s, s);
                const ulonglong2* mr = reinterpret_cast<const ulonglong2*>(Ms + m*12);
                ulonglong2 m0 = mr[0], m1 = mr[1], m2 = mr[2];
                ffma2(acc2[0], m0.x, s2v); ffma2(acc2[1], m0.y, s2v);
                ffma2(acc2[2], m1.x, s2v); ffma2(acc2[3], m1.y, s2v);
                ffma2(acc2[4], m2.x, s2v); ffma2(acc2[5], m2.y, s2v);
            }
        }
    }

    float a0,a1,a2,a3,a4,a5,a6,a7,a8,a9,a10,a11;
    unpack2(acc2[0], a0, a1);  unpack2(acc2[1], a2, a3);
    unpack2(acc2[2], a4, a5);  unpack2(acc2[3], a6, a7);
    unpack2(acc2[4], a8, a9);  unpack2(acc2[5], a10, a11);
    float f0 = a0 + a3*px + a4*py + a5*pz;
    float f1 = a1 + a6*px + a7*py + a8*pz;
    float f2 = a2 + a9*px + a10*py + a11*pz;

    __syncthreads();
    float* orow = &Ssm[tid*13];
    orow[0] = f0; orow[1] = f1; orow[2] = f2;
    orow[3] = f0 - cvx; orow[4] = f1 - cvy; orow[5] = f2 - cvz;
#pragma unroll
    for (int d = 6; d < 13; d++) orow[d] = 0.0f;
    __syncthreads();

    float* og = dxp + ((long)b*NP_ + n0)*13;
    for (int idx = tid; idx < PPB*13; idx += 256) og[idx] = Ssm[idx];
}

// ---------------------------------------------------------------------------
extern "C" void kernel_launch(void* const* d_in, const int* in_sizes, int n_in,
                              void* d_out, int out_size) {
    const float* t   = (const float*)d_in[0];
    const float* x_p = (const float*)d_in[1];
    const float* x_o = (const float*)d_in[2];
    const float* S   = (const float*)d_in[3];
    const float* ew0 = (const float*)d_in[4];  const float* eb0 = (const float*)d_in[5];
    const float* ew1 = (const float*)d_in[6];  const float* eb1 = (const float*)d_in[7];
    const float* ew2 = (const float*)d_in[8];  const float* eb2 = (const float*)d_in[9];
    const float* vw0 = (const float*)d_in[10]; const float* vb0 = (const float*)d_in[11];
    const float* vw1 = (const float*)d_in[12]; const float* vb1 = (const float*)d_in[13];
    const float* vw2 = (const float*)d_in[14]; const float* vb2 = (const float*)d_in[15];
    const float* vw3 = (const float*)d_in[16]; const float* vb3 = (const float*)d_in[17];
    const float* ow0 = (const float*)d_in[18]; const float* ob0 = (const float*)d_in[19];
    const float* ow1 = (const float*)d_in[20]; const float* ob1 = (const float*)d_in[21];
    const float* ow2 = (const float*)d_in[22]; const float* ob2 = (const float*)d_in[23];
    const float* ow3 = (const float*)d_in[24]; const float* ob3 = (const float*)d_in[25];

    float* out = (float*)d_out;
    float* dxp = out;
    float* dxo = out + (long)B_*NP_*13;

    float* Anorm; cudaGetSymbolAddress((void**)&Anorm, g_Anorm);
    float* mobjp; cudaGetSymbolAddress((void**)&mobjp, g_mobjp);
    float* objM;  cudaGetSymbolAddress((void**)&objM,  g_objM);

    k0_obj_prep<<<B_, NO_>>>(x_o, Anorm, objM, dxo);

    k2_edge<<<B_*NO_*2, 128>>>(x_o, t, Anorm, ew0, eb0, ew1, eb1, ew2, eb2, mobjp);

    k3_node<<<128, 256>>>(x_o, mobjp, t,
                          vw0, vb0, vw1, vb1, vw2, vb2, vw3, vb3,
                          ow0, ob0, ow1, ob1, ow2, ob2, ow3, ob3,
                          dxo);

    size_t sm4 = (768 + PPB*SPAD) * sizeof(float);
    cudaFuncSetAttribute(k4_particles, cudaFuncAttributeMaxDynamicSharedMemorySize, (int)sm4);
    k4_particles<<<dim3(NP_/PPB, B_), 256, sm4>>>(x_p, S, objM, dxp);
}